// round 11
// baseline (speedup 1.0000x reference)
#include <cuda_runtime.h>
#include <cuda_fp16.h>
#include <cstdint>

#define BATCH 8192
#define NNODE 30
#define FEAT  256
#define MROWS (BATCH * NNODE)   // 245760
#define TROWS 96
#define NTILES (MROWS / TROWS)  // 2560
#define PGRID 148

// ---------------- scratch (device globals) ----------------
__device__ float  g_adj[(size_t)BATCH * NNODE * NNODE];  // 29.5 MB
__device__ __half g_y1[(size_t)MROWS * FEAT];
__device__ __half g_h1[(size_t)MROWS * FEAT];
__device__ __half g_u2[(size_t)MROWS * FEAT];
__device__ __half g_w1[FEAT * FEAT], g_w2[FEAT * FEAT];

// ==================== helpers ====================
__device__ __forceinline__ uint32_t smem_to_u32(const void* p) {
    uint32_t a;
    asm("{ .reg .u64 t; cvta.to.shared.u64 t, %1; cvt.u32.u64 %0, t; }" : "=r"(a) : "l"(p));
    return a;
}
__device__ __forceinline__ void cpasync16(uint32_t saddr, const void* g) {
    asm volatile("cp.async.cg.shared.global [%0], [%1], 16;" :: "r"(saddr), "l"(g));
}
__device__ __forceinline__ void ldsm4(uint32_t* r, uint32_t addr) {
    asm volatile("ldmatrix.sync.aligned.m8n8.x4.shared.b16 {%0,%1,%2,%3}, [%4];"
        : "=r"(r[0]), "=r"(r[1]), "=r"(r[2]), "=r"(r[3]) : "r"(addr));
}
__device__ __forceinline__ void mma_f16(float* d, const uint32_t* a, uint32_t b0, uint32_t b1) {
    asm volatile(
        "mma.sync.aligned.m16n8k16.row.col.f32.f16.f16.f32 "
        "{%0,%1,%2,%3}, {%4,%5,%6,%7}, {%8,%9}, {%0,%1,%2,%3};"
        : "+f"(d[0]), "+f"(d[1]), "+f"(d[2]), "+f"(d[3])
        : "r"(a[0]), "r"(a[1]), "r"(a[2]), "r"(a[3]), "r"(b0), "r"(b1));
}
__device__ __forceinline__ unsigned long long pk2(float x, float y) {
    unsigned long long r;
    asm("mov.b64 %0, {%1, %2};" : "=l"(r) : "f"(x), "f"(y));
    return r;
}
__device__ __forceinline__ void upk2(unsigned long long v, float& x, float& y) {
    asm("mov.b64 {%0, %1}, %2;" : "=f"(x), "=f"(y) : "l"(v));
}
__device__ __forceinline__ unsigned long long fma2(unsigned long long a,
                                                   unsigned long long b,
                                                   unsigned long long c) {
    unsigned long long d;
    asm("fma.rn.f32x2 %0, %1, %2, %3;" : "=l"(d) : "l"(a), "l"(b), "l"(c));
    return d;
}

// =====================================================================
// prep_w: transpose W1/W2 to [N,K] K-major fp16
// =====================================================================
__global__ void prep_w(const float* __restrict__ W1, const float* __restrict__ W2,
                       __half* __restrict__ w1, __half* __restrict__ w2) {
    const int n = blockIdx.x, k = threadIdx.x;
    w1[n * 256 + k] = __float2half_rn(W1[k * 256 + n]);
    w2[n * 256 + k] = __float2half_rn(W2[k * 256 + n]);
}

// =====================================================================
// k_prep: adj = mean(graph, bands); y1 = adj @ x -> fp16
// =====================================================================
__global__ __launch_bounds__(128)
void k_prep(const float* __restrict__ graph, const float* __restrict__ x,
            float* __restrict__ adj_out, __half* __restrict__ y1) {
    __shared__ float adj_s[900];
    const int tid = threadIdx.x;
    const size_t b = blockIdx.x;

    const float* gp = graph + b * 4500;
    float* ao = adj_out + b * 900;
    for (int e = tid; e < 900; e += 128) {
        float s = 0.2f * (gp[e] + gp[e + 900] + gp[e + 1800] + gp[e + 2700] + gp[e + 3600]);
        adj_s[e] = s;
        ao[e] = s;
    }

    const int j = tid * 2;
    const float* xp = x + b * 7680 + j;
    unsigned long long xr[30];
    #pragma unroll
    for (int k = 0; k < 30; ++k) {
        float2 v = *(const float2*)(xp + (size_t)k * 256);
        xr[k] = pk2(v.x, v.y);
    }
    __syncthreads();

    #pragma unroll 1
    for (int i = 0; i < 30; ++i) {
        unsigned long long acc = 0ULL;
        const float* ar = adj_s + i * 30;
        #pragma unroll
        for (int k = 0; k < 30; ++k) {
            float a = ar[k];
            acc = fma2(pk2(a, a), xr[k], acc);
        }
        float y0, yy;
        upk2(acc, y0, yy);
        *(__half2*)(y1 + (b * 30 + i) * 256 + j) = __floats2half2_rn(y0, yy);
    }
}

// =====================================================================
// Persistent GEMM: C[96-tile,256] = A @ W^T(K-major), fp16, W RESIDENT.
// grid=148, 384 threads / 12 warps (3 warp_m x 4 warp_n), warp tile 32x64.
// Per k16: 6 ldsm4 -> 16 HMMA (0.375 ldsm/MMA). One barrier per tile
// (256 HMMA/warp between barriers). A double-buffered 48KB tiles.
// MODE 1: Out = relu(C+bias) -> fp16 ;  MODE 2: Out = C -> fp16
// smem: W [0,131072) 16 chunks 8KB; A [131072,+2x49152); bias [229376)
// =====================================================================
#define PSM_W    0u
#define PSM_A    131072u
#define PSM_BIAS 229376u
#define PSM_TOTAL 230400

template <int MODE>
__global__ __launch_bounds__(384, 1)
void gemm_persist(const __half* __restrict__ A, const __half* __restrict__ W,
                  const float* __restrict__ bias, __half* __restrict__ Out) {
    extern __shared__ char smem[];
    const uint32_t sb = smem_to_u32(smem);
    const int tid = threadIdx.x, lane = tid & 31, wid = tid >> 5;
    const int warp_m = wid >> 2, warp_n = wid & 3;   // 3 x 4

    // ---- W resident load: 16 chunks x 8KB ----
    #pragma unroll
    for (int u = tid; u < 8192; u += 384) {
        int kc = u >> 9, v = u & 511;
        int n = v >> 1, half = v & 1;
        int row = n & 63, sub = n >> 6;
        uint32_t off = (uint32_t)kc * 8192u + (uint32_t)(row * 128)
                     + (((uint32_t)(sub * 32 + half * 16)) ^ ((uint32_t)(row & 7) << 4));
        cpasync16(sb + PSM_W + off, W + (size_t)n * 256 + (size_t)kc * 16 + half * 8);
    }
    asm volatile("cp.async.commit_group;" ::: "memory");
    if (MODE == 1 && tid < 256) ((float*)(smem + PSM_BIAS))[tid] = bias[tid];

    // ---- A tile loader: 48KB = 4 chunks [96 x 128B] SW128 ----
    auto aload = [&](int tile, int stage) {
        const __half* gA = A + (size_t)tile * TROWS * 256;
        uint32_t st = sb + PSM_A + (uint32_t)stage * 49152u;
        #pragma unroll
        for (int u = tid; u < 3072; u += 384) {
            int row = u >> 5, s = u & 31;
            int c = s >> 3, ss = s & 7;
            uint32_t off = (uint32_t)c * 12288u + (uint32_t)(row * 128)
                         + (((uint32_t)ss * 16u) ^ ((uint32_t)(row & 7) << 4));
            cpasync16(st + off, gA + (size_t)row * 256 + s * 8);
        }
        asm volatile("cp.async.commit_group;" ::: "memory");
    };

    // ---- ldmatrix addressing ----
    const int matv = lane >> 3;
    const int rA0 = warp_m * 32 + (matv & 1) * 8 + (lane & 7);
    const int kAoff = (matv >> 1) * 16;
    const int nB0 = warp_n * 64 + matv * 8 + (lane & 7);
    const uint32_t xorv = (uint32_t)((lane & 7) << 4);
    const int g = lane >> 2, cq = (lane & 3) * 2;

    int tile = blockIdx.x;
    aload(tile, 0);
    int it = 0;

    #pragma unroll 1
    for (; tile < NTILES; tile += PGRID, ++it) {
        const int stage = it & 1;
        asm volatile("cp.async.wait_group 0;" ::: "memory");
        __syncthreads();
        if (tile + PGRID < NTILES) aload(tile + PGRID, stage ^ 1);

        const uint32_t ab = sb + PSM_A + (uint32_t)stage * 49152u;
        float acc[2][8][4];
        #pragma unroll
        for (int m = 0; m < 2; ++m)
            #pragma unroll
            for (int j = 0; j < 8; ++j)
                #pragma unroll
                for (int q = 0; q < 4; ++q) acc[m][j][q] = 0.f;

        #pragma unroll 4
        for (int kc = 0; kc < 16; ++kc) {
            const uint32_t abase = ab + (uint32_t)(kc >> 2) * 12288u;
            const uint32_t aco = ((uint32_t)((kc & 3) * 32 + kAoff)) ^ xorv;
            uint32_t a_f[2][4];
            #pragma unroll
            for (int mt = 0; mt < 2; ++mt)
                ldsm4(a_f[mt], abase + (uint32_t)((rA0 + mt * 16) * 128) + aco);

            const uint32_t wst = sb + PSM_W + (uint32_t)kc * 8192u;
            #pragma unroll
            for (int jb = 0; jb < 2; ++jb) {
                const int n = nB0 + jb * 32;
                const uint32_t ro = (uint32_t)((n & 63) * 128);
                const uint32_t base = (uint32_t)((n >> 6) * 32);
                uint32_t b0[4], b1[4];
                ldsm4(b0, wst + ro + (base ^ xorv));
                ldsm4(b1, wst + ro + ((base + 16u) ^ xorv));
                #pragma unroll
                for (int mt = 0; mt < 2; ++mt)
                    #pragma unroll
                    for (int jj = 0; jj < 4; ++jj)
                        mma_f16(acc[mt][jb * 4 + jj], a_f[mt], b0[jj], b1[jj]);
            }
        }

        // ---- epilogue ----
        #pragma unroll
        for (int mt = 0; mt < 2; ++mt) {
            const size_t r0 = (size_t)tile * TROWS + warp_m * 32 + mt * 16 + g;
            #pragma unroll
            for (int j = 0; j < 8; ++j) {
                const int col = warp_n * 64 + j * 8 + cq;
                if (MODE == 1) {
                    const float* bs = (const float*)(smem + PSM_BIAS);
                    float bb0 = bs[col], bb1 = bs[col + 1];
                    *(__half2*)(Out + r0 * 256 + col) = __floats2half2_rn(
                        fmaxf(acc[mt][j][0] + bb0, 0.f), fmaxf(acc[mt][j][1] + bb1, 0.f));
                    *(__half2*)(Out + (r0 + 8) * 256 + col) = __floats2half2_rn(
                        fmaxf(acc[mt][j][2] + bb0, 0.f), fmaxf(acc[mt][j][3] + bb1, 0.f));
                } else {
                    *(__half2*)(Out + r0 * 256 + col) =
                        __floats2half2_rn(acc[mt][j][0], acc[mt][j][1]);
                    *(__half2*)(Out + (r0 + 8) * 256 + col) =
                        __floats2half2_rn(acc[mt][j][2], acc[mt][j][3]);
                }
            }
        }
    }
}

// =====================================================================
// k_final: g2 = adj @ u2; p = relu(g2+b2).wlin; xl = relu(p+blin);
//          out = xl @ W_head^T + b_head.  u2 in fp16.
// =====================================================================
__global__ __launch_bounds__(512)
void k_final(const float* __restrict__ adj, const __half* __restrict__ u2,
             const float* __restrict__ b2g, const float* __restrict__ wling,
             const float* __restrict__ bling, const float* __restrict__ Wheadg,
             const float* __restrict__ bheadg, float* __restrict__ out) {
    __shared__ float adj_s[4 * 960];
    __shared__ float red[4][30][4];
    const int tid = threadIdx.x;
    const int b = tid >> 7, t2 = tid & 127, w = t2 >> 5;
    const size_t b0 = (size_t)blockIdx.x * 4;

    for (int e = tid; e < 3600; e += 512) {
        int bb = e / 900, i = e - bb * 900;
        adj_s[bb * 960 + (i / 30) * 32 + (i % 30)] = adj[(b0 + bb) * 900 + i];
    }

    const int j = t2 * 2;
    const __half* up = u2 + (b0 + b) * 7680 + j;
    unsigned long long uk[30];
    #pragma unroll
    for (int k = 0; k < 30; ++k) {
        float2 v = __half22float2(*(const __half2*)(up + (size_t)k * 256));
        uk[k] = pk2(v.x, v.y);
    }
    const float b2v0 = __ldg(b2g + j), b2v1 = __ldg(b2g + j + 1);
    const float wl0 = __ldg(wling + j), wl1 = __ldg(wling + j + 1);
    __syncthreads();

    const float* ar = adj_s + b * 960;
    #pragma unroll 1
    for (int i = 0; i < 30; ++i) {
        unsigned long long acc = 0ULL;
        #pragma unroll
        for (int k = 0; k < 30; ++k) {
            float a = ar[i * 32 + k];
            acc = fma2(pk2(a, a), uk[k], acc);
        }
        float s0, s1;
        upk2(acc, s0, s1);
        float p = fmaxf(s0 + b2v0, 0.f) * wl0 + fmaxf(s1 + b2v1, 0.f) * wl1;
        #pragma unroll
        for (int o = 16; o > 0; o >>= 1) p += __shfl_xor_sync(0xffffffffu, p, o);
        if ((t2 & 31) == 0) red[b][i][w] = p;
    }
    __syncthreads();

    if (tid < 36) {
        const int bb = tid / 9, c = tid - bb * 9;
        const float bl = __ldg(bling);
        float s = __ldg(bheadg + c);
        #pragma unroll
        for (int i = 0; i < 30; ++i) {
            float xl = fmaxf(red[bb][i][0] + red[bb][i][1] + red[bb][i][2] + red[bb][i][3] + bl, 0.f);
            s = fmaf(xl, __ldg(Wheadg + c * 30 + i), s);
        }
        out[(b0 + bb) * 9 + c] = s;
    }
}

// =====================================================================
extern "C" void kernel_launch(void* const* d_in, const int* in_sizes, int n_in,
                              void* d_out, int out_size) {
    const float* real  = (const float*)d_in[0];
    const float* graph = (const float*)d_in[2];
    const float* W1    = (const float*)d_in[3];
    const float* b1    = (const float*)d_in[4];
    const float* W2    = (const float*)d_in[5];
    const float* b2    = (const float*)d_in[6];
    const float* wlin  = (const float*)d_in[7];
    const float* blin  = (const float*)d_in[8];
    const float* Whead = (const float*)d_in[9];
    const float* bhead = (const float*)d_in[10];
    float* out = (float*)d_out;

    float *adj_p;
    __half *y1_p, *h1_p, *u2_p, *w1_p, *w2_p;
    cudaGetSymbolAddress((void**)&adj_p, g_adj);
    cudaGetSymbolAddress((void**)&y1_p,  g_y1);
    cudaGetSymbolAddress((void**)&h1_p,  g_h1);
    cudaGetSymbolAddress((void**)&u2_p,  g_u2);
    cudaGetSymbolAddress((void**)&w1_p,  g_w1);
    cudaGetSymbolAddress((void**)&w2_p,  g_w2);

    cudaFuncSetAttribute(gemm_persist<1>, cudaFuncAttributeMaxDynamicSharedMemorySize, PSM_TOTAL);
    cudaFuncSetAttribute(gemm_persist<2>, cudaFuncAttributeMaxDynamicSharedMemorySize, PSM_TOTAL);

    // 1. weight transpose to fp16 [N,K]
    prep_w<<<256, 256>>>(W1, W2, w1_p, w2_p);
    // 2. adj = mean(graph); y1 = adj @ real (fp16)
    k_prep<<<BATCH, 128>>>(graph, real, adj_p, y1_p);
    // 3. h1 = relu(y1 @ W1 + b1)  (persistent, W1 resident)
    gemm_persist<1><<<PGRID, 384, PSM_TOTAL>>>(y1_p, w1_p, b1, h1_p);
    // 4. u2 = h1 @ W2             (persistent, W2 resident)
    gemm_persist<2><<<PGRID, 384, PSM_TOTAL>>>(h1_p, w2_p, nullptr, u2_p);
    // 5. fused: g2 = adj@u2; relu(+b2).wlin; relu(+blin); head -> out
    k_final<<<BATCH / 4, 512>>>(adj_p, u2_p, b2, wlin, blin, Whead, bhead, out);
}

// round 12
// speedup vs baseline: 1.0115x; 1.0115x over previous
#include <cuda_runtime.h>
#include <cuda_fp16.h>
#include <cstdint>

#define BATCH 8192
#define NNODE 30
#define FEAT  256
#define MROWS (BATCH * NNODE)   // 245760
#define NTILES (MROWS / 64)     // 3840
#define PGRID 148

// ---------------- scratch (device globals) ----------------
__device__ float  g_adj[(size_t)BATCH * NNODE * NNODE];  // 29.5 MB
__device__ __half g_y1[(size_t)MROWS * FEAT];
__device__ __half g_h1[(size_t)MROWS * FEAT];
__device__ __half g_u2[(size_t)MROWS * FEAT];
__device__ __half g_w1[FEAT * FEAT], g_w2[FEAT * FEAT];

// ==================== helpers ====================
__device__ __forceinline__ uint32_t smem_to_u32(const void* p) {
    uint32_t a;
    asm("{ .reg .u64 t; cvta.to.shared.u64 t, %1; cvt.u32.u64 %0, t; }" : "=r"(a) : "l"(p));
    return a;
}
__device__ __forceinline__ void cpasync16(uint32_t saddr, const void* g) {
    asm volatile("cp.async.cg.shared.global [%0], [%1], 16;" :: "r"(saddr), "l"(g));
}
__device__ __forceinline__ void ldsm4(uint32_t* r, uint32_t addr) {
    asm volatile("ldmatrix.sync.aligned.m8n8.x4.shared.b16 {%0,%1,%2,%3}, [%4];"
        : "=r"(r[0]), "=r"(r[1]), "=r"(r[2]), "=r"(r[3]) : "r"(addr));
}
__device__ __forceinline__ void mma_f16(float* d, const uint32_t* a, uint32_t b0, uint32_t b1) {
    asm volatile(
        "mma.sync.aligned.m16n8k16.row.col.f32.f16.f16.f32 "
        "{%0,%1,%2,%3}, {%4,%5,%6,%7}, {%8,%9}, {%0,%1,%2,%3};"
        : "+f"(d[0]), "+f"(d[1]), "+f"(d[2]), "+f"(d[3])
        : "r"(a[0]), "r"(a[1]), "r"(a[2]), "r"(a[3]), "r"(b0), "r"(b1));
}
__device__ __forceinline__ unsigned long long pk2(float x, float y) {
    unsigned long long r;
    asm("mov.b64 %0, {%1, %2};" : "=l"(r) : "f"(x), "f"(y));
    return r;
}
__device__ __forceinline__ void upk2(unsigned long long v, float& x, float& y) {
    asm("mov.b64 {%0, %1}, %2;" : "=f"(x), "=f"(y) : "l"(v));
}
__device__ __forceinline__ unsigned long long fma2(unsigned long long a,
                                                   unsigned long long b,
                                                   unsigned long long c) {
    unsigned long long d;
    asm("fma.rn.f32x2 %0, %1, %2, %3;" : "=l"(d) : "l"(a), "l"(b), "l"(c));
    return d;
}

// =====================================================================
// prep_w: transpose W1/W2 to [N,K] K-major fp16
// =====================================================================
__global__ void prep_w(const float* __restrict__ W1, const float* __restrict__ W2,
                       __half* __restrict__ w1, __half* __restrict__ w2) {
    const int n = blockIdx.x, k = threadIdx.x;
    w1[n * 256 + k] = __float2half_rn(W1[k * 256 + n]);
    w2[n * 256 + k] = __float2half_rn(W2[k * 256 + n]);
}

// =====================================================================
// k_prep: adj = mean(graph, bands); y1 = adj @ x -> fp16
// =====================================================================
__global__ __launch_bounds__(128)
void k_prep(const float* __restrict__ graph, const float* __restrict__ x,
            float* __restrict__ adj_out, __half* __restrict__ y1) {
    __shared__ float adj_s[900];
    const int tid = threadIdx.x;
    const size_t b = blockIdx.x;

    const float* gp = graph + b * 4500;
    float* ao = adj_out + b * 900;
    for (int e = tid; e < 900; e += 128) {
        float s = 0.2f * (gp[e] + gp[e + 900] + gp[e + 1800] + gp[e + 2700] + gp[e + 3600]);
        adj_s[e] = s;
        ao[e] = s;
    }

    const int j = tid * 2;
    const float* xp = x + b * 7680 + j;
    unsigned long long xr[30];
    #pragma unroll
    for (int k = 0; k < 30; ++k) {
        float2 v = *(const float2*)(xp + (size_t)k * 256);
        xr[k] = pk2(v.x, v.y);
    }
    __syncthreads();

    #pragma unroll 1
    for (int i = 0; i < 30; ++i) {
        unsigned long long acc = 0ULL;
        const float* ar = adj_s + i * 30;
        #pragma unroll
        for (int k = 0; k < 30; ++k) {
            float a = ar[k];
            acc = fma2(pk2(a, a), xr[k], acc);
        }
        float y0, yy;
        upk2(acc, y0, yy);
        *(__half2*)(y1 + (b * 30 + i) * 256 + j) = __floats2half2_rn(y0, yy);
    }
}

// =====================================================================
// Persistent GEMM: C[64-tile,256] = A @ W^T(K-major), fp16, W RESIDENT.
// grid=148, 512 threads / 16 warps (2 warp_m x 8 warp_n), warp tile 32x32.
// Register double-buffered fragments: ldsm(kc+1) issued before HMMA(kc)
// to hide ldsm latency behind tensor work. One barrier per tile.
// MODE 1: Out = relu(C+bias) -> fp16 ;  MODE 2: Out = C -> fp16
// smem: W [0,131072) 16 chunks 8KB; A [131072,+2x32768); bias [196608)
// =====================================================================
#define PSM_W    0u
#define PSM_A    131072u
#define PSM_BIAS 196608u
#define PSM_TOTAL 197632

template <int MODE>
__global__ __launch_bounds__(512, 1)
void gemm_persist(const __half* __restrict__ A, const __half* __restrict__ W,
                  const float* __restrict__ bias, __half* __restrict__ Out) {
    extern __shared__ char smem[];
    const uint32_t sb = smem_to_u32(smem);
    const int tid = threadIdx.x, lane = tid & 31, wid = tid >> 5;
    const int warp_m = wid & 1, warp_n = wid >> 1;   // 2 x 8

    // ---- W resident load: 16 chunks x 8KB ----
    #pragma unroll
    for (int u = tid; u < 8192; u += 512) {
        int kc = u >> 9, v = u & 511;
        int n = v >> 1, half = v & 1;
        int row = n & 63, sub = n >> 6;
        uint32_t off = (uint32_t)kc * 8192u + (uint32_t)(row * 128)
                     + (((uint32_t)(sub * 32 + half * 16)) ^ ((uint32_t)(row & 7) << 4));
        cpasync16(sb + PSM_W + off, W + (size_t)n * 256 + (size_t)kc * 16 + half * 8);
    }
    asm volatile("cp.async.commit_group;" ::: "memory");
    if (MODE == 1 && tid < 256) ((float*)(smem + PSM_BIAS))[tid] = bias[tid];

    // ---- A tile loader: 32KB = 4 chunks [64 x 128B] SW128 ----
    auto aload = [&](int tile, int stage) {
        const __half* gA = A + (size_t)tile * 64 * 256;
        uint32_t st = sb + PSM_A + (uint32_t)stage * 32768u;
        #pragma unroll
        for (int u = tid; u < 2048; u += 512) {
            int row = u >> 5, s = u & 31;
            int c = s >> 3, ss = s & 7;
            uint32_t off = (uint32_t)c * 8192u + (uint32_t)(row * 128)
                         + (((uint32_t)ss * 16u) ^ ((uint32_t)(row & 7) << 4));
            cpasync16(st + off, gA + (size_t)row * 256 + s * 8);
        }
        asm volatile("cp.async.commit_group;" ::: "memory");
    };

    // ---- ldmatrix addressing ----
    const int matv = lane >> 3;
    const int rA0 = warp_m * 32 + (matv & 1) * 8 + (lane & 7);
    const int kAoff = (matv >> 1) * 16;
    const int nB0 = warp_n * 32 + matv * 8 + (lane & 7);
    const uint32_t roB = (uint32_t)((nB0 & 63) * 128);
    const uint32_t baseB = (uint32_t)((nB0 >> 6) * 32);
    const uint32_t xorv = (uint32_t)((lane & 7) << 4);
    const int g = lane >> 2, cq = (lane & 3) * 2;

    int tile = blockIdx.x;
    aload(tile, 0);
    int it = 0;

    #pragma unroll 1
    for (; tile < NTILES; tile += PGRID, ++it) {
        const int stage = it & 1;
        asm volatile("cp.async.wait_group 0;" ::: "memory");
        __syncthreads();
        if (tile + PGRID < NTILES) aload(tile + PGRID, stage ^ 1);

        const uint32_t ab = sb + PSM_A + (uint32_t)stage * 32768u;
        float acc[2][4][4];
        #pragma unroll
        for (int m = 0; m < 2; ++m)
            #pragma unroll
            for (int j = 0; j < 4; ++j)
                #pragma unroll
                for (int q = 0; q < 4; ++q) acc[m][j][q] = 0.f;

        // ---- fragment double buffers ----
        uint32_t a_f[2][2][4], bf0[2][4], bf1[2][4];
        auto ldfrag = [&](int kc, int pb) {
            const uint32_t abase = ab + (uint32_t)(kc >> 2) * 8192u;
            const uint32_t aco = ((uint32_t)((kc & 3) * 32 + kAoff)) ^ xorv;
            ldsm4(a_f[pb][0], abase + (uint32_t)(rA0 * 128) + aco);
            ldsm4(a_f[pb][1], abase + (uint32_t)((rA0 + 16) * 128) + aco);
            const uint32_t wst = sb + PSM_W + (uint32_t)kc * 8192u;
            ldsm4(bf0[pb], wst + roB + (baseB ^ xorv));
            ldsm4(bf1[pb], wst + roB + ((baseB + 16u) ^ xorv));
        };

        ldfrag(0, 0);
        #pragma unroll
        for (int kc = 0; kc < 16; ++kc) {
            const int pb = kc & 1;
            if (kc < 15) ldfrag(kc + 1, pb ^ 1);   // hide ldsm latency behind HMMA
            #pragma unroll
            for (int mt = 0; mt < 2; ++mt)
                #pragma unroll
                for (int jj = 0; jj < 4; ++jj)
                    mma_f16(acc[mt][jj], a_f[pb][mt], bf0[pb][jj], bf1[pb][jj]);
        }

        // ---- epilogue ----
        #pragma unroll
        for (int mt = 0; mt < 2; ++mt) {
            const size_t r0 = (size_t)tile * 64 + warp_m * 32 + mt * 16 + g;
            #pragma unroll
            for (int j = 0; j < 4; ++j) {
                const int col = warp_n * 32 + j * 8 + cq;
                if (MODE == 1) {
                    const float* bs = (const float*)(smem + PSM_BIAS);
                    float bb0 = bs[col], bb1 = bs[col + 1];
                    *(__half2*)(Out + r0 * 256 + col) = __floats2half2_rn(
                        fmaxf(acc[mt][j][0] + bb0, 0.f), fmaxf(acc[mt][j][1] + bb1, 0.f));
                    *(__half2*)(Out + (r0 + 8) * 256 + col) = __floats2half2_rn(
                        fmaxf(acc[mt][j][2] + bb0, 0.f), fmaxf(acc[mt][j][3] + bb1, 0.f));
                } else {
                    *(__half2*)(Out + r0 * 256 + col) =
                        __floats2half2_rn(acc[mt][j][0], acc[mt][j][1]);
                    *(__half2*)(Out + (r0 + 8) * 256 + col) =
                        __floats2half2_rn(acc[mt][j][2], acc[mt][j][3]);
                }
            }
        }
    }
}

// =====================================================================
// k_final: g2 = adj @ u2; p = relu(g2+b2).wlin; xl = relu(p+blin);
//          out = xl @ W_head^T + b_head.  u2 in fp16.
// =====================================================================
__global__ __launch_bounds__(512)
void k_final(const float* __restrict__ adj, const __half* __restrict__ u2,
             const float* __restrict__ b2g, const float* __restrict__ wling,
             const float* __restrict__ bling, const float* __restrict__ Wheadg,
             const float* __restrict__ bheadg, float* __restrict__ out) {
    __shared__ float adj_s[4 * 960];
    __shared__ float red[4][30][4];
    const int tid = threadIdx.x;
    const int b = tid >> 7, t2 = tid & 127, w = t2 >> 5;
    const size_t b0 = (size_t)blockIdx.x * 4;

    for (int e = tid; e < 3600; e += 512) {
        int bb = e / 900, i = e - bb * 900;
        adj_s[bb * 960 + (i / 30) * 32 + (i % 30)] = adj[(b0 + bb) * 900 + i];
    }

    const int j = t2 * 2;
    const __half* up = u2 + (b0 + b) * 7680 + j;
    unsigned long long uk[30];
    #pragma unroll
    for (int k = 0; k < 30; ++k) {
        float2 v = __half22float2(*(const __half2*)(up + (size_t)k * 256));
        uk[k] = pk2(v.x, v.y);
    }
    const float b2v0 = __ldg(b2g + j), b2v1 = __ldg(b2g + j + 1);
    const float wl0 = __ldg(wling + j), wl1 = __ldg(wling + j + 1);
    __syncthreads();

    const float* ar = adj_s + b * 960;
    #pragma unroll 1
    for (int i = 0; i < 30; ++i) {
        unsigned long long acc = 0ULL;
        #pragma unroll
        for (int k = 0; k < 30; ++k) {
            float a = ar[i * 32 + k];
            acc = fma2(pk2(a, a), uk[k], acc);
        }
        float s0, s1;
        upk2(acc, s0, s1);
        float p = fmaxf(s0 + b2v0, 0.f) * wl0 + fmaxf(s1 + b2v1, 0.f) * wl1;
        #pragma unroll
        for (int o = 16; o > 0; o >>= 1) p += __shfl_xor_sync(0xffffffffu, p, o);
        if ((t2 & 31) == 0) red[b][i][w] = p;
    }
    __syncthreads();

    if (tid < 36) {
        const int bb = tid / 9, c = tid - bb * 9;
        const float bl = __ldg(bling);
        float s = __ldg(bheadg + c);
        #pragma unroll
        for (int i = 0; i < 30; ++i) {
            float xl = fmaxf(red[bb][i][0] + red[bb][i][1] + red[bb][i][2] + red[bb][i][3] + bl, 0.f);
            s = fmaf(xl, __ldg(Wheadg + c * 30 + i), s);
        }
        out[(b0 + bb) * 9 + c] = s;
    }
}

// =====================================================================
extern "C" void kernel_launch(void* const* d_in, const int* in_sizes, int n_in,
                              void* d_out, int out_size) {
    const float* real  = (const float*)d_in[0];
    const float* graph = (const float*)d_in[2];
    const float* W1    = (const float*)d_in[3];
    const float* b1    = (const float*)d_in[4];
    const float* W2    = (const float*)d_in[5];
    const float* b2    = (const float*)d_in[6];
    const float* wlin  = (const float*)d_in[7];
    const float* blin  = (const float*)d_in[8];
    const float* Whead = (const float*)d_in[9];
    const float* bhead = (const float*)d_in[10];
    float* out = (float*)d_out;

    float *adj_p;
    __half *y1_p, *h1_p, *u2_p, *w1_p, *w2_p;
    cudaGetSymbolAddress((void**)&adj_p, g_adj);
    cudaGetSymbolAddress((void**)&y1_p,  g_y1);
    cudaGetSymbolAddress((void**)&h1_p,  g_h1);
    cudaGetSymbolAddress((void**)&u2_p,  g_u2);
    cudaGetSymbolAddress((void**)&w1_p,  g_w1);
    cudaGetSymbolAddress((void**)&w2_p,  g_w2);

    cudaFuncSetAttribute(gemm_persist<1>, cudaFuncAttributeMaxDynamicSharedMemorySize, PSM_TOTAL);
    cudaFuncSetAttribute(gemm_persist<2>, cudaFuncAttributeMaxDynamicSharedMemorySize, PSM_TOTAL);

    // 1. weight transpose to fp16 [N,K]
    prep_w<<<256, 256>>>(W1, W2, w1_p, w2_p);
    // 2. adj = mean(graph); y1 = adj @ real (fp16)
    k_prep<<<BATCH, 128>>>(graph, real, adj_p, y1_p);
    // 3. h1 = relu(y1 @ W1 + b1)  (persistent, W1 resident)
    gemm_persist<1><<<PGRID, 512, PSM_TOTAL>>>(y1_p, w1_p, b1, h1_p);
    // 4. u2 = h1 @ W2             (persistent, W2 resident)
    gemm_persist<2><<<PGRID, 512, PSM_TOTAL>>>(h1_p, w2_p, nullptr, u2_p);
    // 5. fused: g2 = adj@u2; relu(+b2).wlin; relu(+blin); head -> out
    k_final<<<BATCH / 4, 512>>>(adj_p, u2_p, b2, wlin, blin, Whead, bhead, out);
}